// round 16
// baseline (speedup 1.0000x reference)
#include <cuda_runtime.h>
#include <cuda_bf16.h>
#include <mma.h>
using namespace nvcuda;

constexpr int Bn = 64, Kn = 100, Fn = 128, En = 200, JP = 128;
constexpr int EP = 208;                 // padded E (13 n-tiles)
constexpr int MT = 112;                 // padded M (7 m-tiles)
constexpr int LDA = 136, LDB = 208;     // smem leading dims (mult of 8 bf16)
constexpr int LDR = 112;                // Rbuf leading dim (j), mult of 4

__device__ float g_UL[Bn * MT * EP];    // left proj (NO bias), row-major [b][row][e]
__device__ float g_RT[Bn * EP * JP];    // right proj transposed: [b][e][j]

// ---------------------------------------------------------------------------
// Kernel 1: 3-pass bf16 split-precision WMMA proj.
// Block = (batch b, chunk c). D[112x208] = x_b[112(pad)x128] @ Wc[128x208(pad)]
// chunk0 -> g_UL row_major (direct).
// chunk1 -> g_RT via smem Rbuf transpose in 4 e-tile groups (coalesced stores).
// ---------------------------------------------------------------------------
__global__ __launch_bounds__(768, 1)
void proj_wmma(const float* __restrict__ x, const float* __restrict__ W) {
    extern __shared__ char smc[];
    __nv_bfloat16* a_hi = (__nv_bfloat16*)smc;        // 112 x 136
    __nv_bfloat16* a_lo = a_hi + MT * LDA;
    __nv_bfloat16* b_hi = a_lo + MT * LDA;            // 128 x 208
    __nv_bfloat16* b_lo = b_hi + Fn * LDB;
    float* Rbuf = (float*)(b_lo + Fn * LDB);          // 64 x 112 f32 (chunk1 only)

    const int b = blockIdx.x, chunk = blockIdx.y;
    const int tid = threadIdx.x, wid = tid >> 5;

    const __nv_bfloat16 zb = __float2bfloat16(0.f);
    for (int i = tid; i < MT * LDA / 2; i += 768) {
        ((__nv_bfloat162*)a_hi)[i] = __nv_bfloat162{zb, zb};
        ((__nv_bfloat162*)a_lo)[i] = __nv_bfloat162{zb, zb};
    }
    for (int i = tid; i < Fn * 8; i += 768) {
        int k = i >> 3, c = En + (i & 7);
        b_hi[k * LDB + c] = zb;
        b_lo[k * LDB + c] = zb;
    }
    __syncthreads();
    {   // stage x -> hi/lo (vectorized)
        const float4* src = (const float4*)(x + b * Kn * Fn);
        for (int idx = tid; idx < Kn * Fn / 4; idx += 768) {
            int r = idx >> 5, kq = idx & 31;
            float4 v = src[idx];
            float vf[4] = {v.x, v.y, v.z, v.w};
            __nv_bfloat16 h[4], l[4];
#pragma unroll
            for (int c = 0; c < 4; c++) {
                h[c] = __float2bfloat16(vf[c]);
                l[c] = __float2bfloat16(vf[c] - __bfloat162float(h[c]));
            }
            int o = r * LDA + 4 * kq;
            *(__nv_bfloat162*)(a_hi + o)     = __nv_bfloat162{h[0], h[1]};
            *(__nv_bfloat162*)(a_hi + o + 2) = __nv_bfloat162{h[2], h[3]};
            *(__nv_bfloat162*)(a_lo + o)     = __nv_bfloat162{l[0], l[1]};
            *(__nv_bfloat162*)(a_lo + o + 2) = __nv_bfloat162{l[2], l[3]};
        }
    }
    {   // stage + convert W chunk (cols 0..199)
        const float4* src = (const float4*)(W + chunk * Fn * En);
        for (int idx = tid; idx < Fn * En / 4; idx += 768) {
            int k = idx / 50, q = idx - k * 50;
            float4 v = src[idx];
            float vf[4] = {v.x, v.y, v.z, v.w};
            __nv_bfloat16 h[4], l[4];
#pragma unroll
            for (int c = 0; c < 4; c++) {
                h[c] = __float2bfloat16(vf[c]);
                l[c] = __float2bfloat16(vf[c] - __bfloat162float(h[c]));
            }
            int o = k * LDB + 4 * q;
            *(__nv_bfloat162*)(b_hi + o)     = __nv_bfloat162{h[0], h[1]};
            *(__nv_bfloat162*)(b_hi + o + 2) = __nv_bfloat162{h[2], h[3]};
            *(__nv_bfloat162*)(b_lo + o)     = __nv_bfloat162{l[0], l[1]};
            *(__nv_bfloat162*)(b_lo + o + 2) = __nv_bfloat162{l[2], l[3]};
        }
    }
    __syncthreads();

    if (chunk == 0) {
        // UL: direct row_major stores to g_UL
        for (int t = wid; t < 7 * 13; t += 24) {
            int tm = t / 13, tn = t - tm * 13;
            wmma::fragment<wmma::accumulator, 16, 16, 16, float> acc;
            wmma::fill_fragment(acc, 0.f);
#pragma unroll
            for (int kt = 0; kt < 8; kt++) {
                wmma::fragment<wmma::matrix_a, 16, 16, 16, __nv_bfloat16, wmma::row_major> ah, al;
                wmma::fragment<wmma::matrix_b, 16, 16, 16, __nv_bfloat16, wmma::row_major> bh, bl;
                wmma::load_matrix_sync(ah, a_hi + tm * 16 * LDA + kt * 16, LDA);
                wmma::load_matrix_sync(al, a_lo + tm * 16 * LDA + kt * 16, LDA);
                wmma::load_matrix_sync(bh, b_hi + kt * 16 * LDB + tn * 16, LDB);
                wmma::load_matrix_sync(bl, b_lo + kt * 16 * LDB + tn * 16, LDB);
                wmma::mma_sync(acc, ah, bh, acc);
                wmma::mma_sync(acc, ah, bl, acc);
                wmma::mma_sync(acc, al, bh, acc);
            }
            float* dst = g_UL + b * MT * EP + tm * 16 * EP + tn * 16;
            wmma::store_matrix_sync(dst, acc, EP, wmma::mem_row_major);
        }
    } else {
        // R: per e-tile group, col_major -> Rbuf, then coalesced copy to g_RT
        for (int g = 0; g < 4; g++) {
            const int tn0 = 4 * g;
            const int width = (g < 3) ? 4 : 1;           // 13 = 4+4+4+1
            for (int t = wid; t < 7 * width; t += 24) {
                int tm = t % 7, tn_l = t / 7;
                int tn = tn0 + tn_l;
                wmma::fragment<wmma::accumulator, 16, 16, 16, float> acc;
                wmma::fill_fragment(acc, 0.f);
#pragma unroll
                for (int kt = 0; kt < 8; kt++) {
                    wmma::fragment<wmma::matrix_a, 16, 16, 16, __nv_bfloat16, wmma::row_major> ah, al;
                    wmma::fragment<wmma::matrix_b, 16, 16, 16, __nv_bfloat16, wmma::row_major> bh, bl;
                    wmma::load_matrix_sync(ah, a_hi + tm * 16 * LDA + kt * 16, LDA);
                    wmma::load_matrix_sync(al, a_lo + tm * 16 * LDA + kt * 16, LDA);
                    wmma::load_matrix_sync(bh, b_hi + kt * 16 * LDB + tn * 16, LDB);
                    wmma::load_matrix_sync(bl, b_lo + kt * 16 * LDB + tn * 16, LDB);
                    wmma::mma_sync(acc, ah, bh, acc);
                    wmma::mma_sync(acc, ah, bl, acc);
                    wmma::mma_sync(acc, al, bh, acc);
                }
                // tile (rows = j = tm*16.., cols = e = tn*16..) stored transposed:
                // Rbuf[e_local][j] with e_local = tn_l*16 + (0..15)
                wmma::store_matrix_sync(Rbuf + (tn_l * 16) * LDR + tm * 16, acc,
                                        LDR, wmma::mem_col_major);
            }
            __syncthreads();
            // coalesced copy: g_RT[b][e0+e_l][0..99] = Rbuf[e_l][0..99]
            const int e0 = 64 * g;
            const int grows = (g < 3) ? 64 : 8;          // e < 200 only
            for (int idx = tid; idx < grows * 25; idx += 768) {
                int e_l = idx / 25, jq = idx - e_l * 25;
                float4 v = *(const float4*)(Rbuf + e_l * LDR + 4 * jq);
                *(float4*)(g_RT + (size_t)(b * EP + e0 + e_l) * JP + 4 * jq) = v;
            }
            __syncthreads();
        }
    }
}

// ---------------------------------------------------------------------------
// Kernel 2 (exact R15 version, measured 37.6us): trio j-mapping.
// lane owns j in {lane, lane+32, lane+64}; j = 96..99 via side dot-products
// BEFORE the main loop; main e4 loop at unroll 2.
// leaky(z) = 0.6 z + 0.4 |z|:
// e_ij = 1.5*(ua04_i + ra04_j) + sum_e a04_e * |u_ie + R_ej| + bias_ij
// ---------------------------------------------------------------------------
template <int R>
__device__ __forceinline__ void do_rows(
    const float* R_sm, const float* xs, const float* u_sm, float* prow,
    const float* a04, const float* ra_sm, const float* Rside,
    const int* lrow, int base, int b, int lane,
    const float* __restrict__ bias, float* __restrict__ out) {

    // aua = 1.5 * (u_r . a04)
    float aua[R];
#pragma unroll
    for (int r = 0; r < R; r++) {
        float s = 0.f;
        const float* up = u_sm + lrow[r] * En;
        for (int e = lane; e < En; e += 32) s = fmaf(up[e], a04[e], s);
#pragma unroll
        for (int o = 16; o; o >>= 1) s += __shfl_xor_sync(0xffffffffu, s, o);
        aua[r] = 1.5f * s;
    }

    // side scores j = 96..99 (conflict-free Rside[js][201])
    float side_sum[R];
#pragma unroll
    for (int r = 0; r < R; r++) {
        side_sum[r] = 0.f;
        const float* up = u_sm + lrow[r] * En;
        const float* bp = bias + (base + lrow[r]) * Kn;
#pragma unroll
        for (int js = 0; js < 4; js++) {
            const float* rs = Rside + js * 201;
            float s = 0.f;
            for (int e = lane; e < En; e += 32)
                s = fmaf(fabsf(up[e] + rs[e]), a04[e], s);
#pragma unroll
            for (int o = 16; o; o >>= 1) s += __shfl_xor_sync(0xffffffffu, s, o);
            int j = 96 + js;
            float pv = __expf(aua[r] + ra_sm[j] + s + bp[j]);
            side_sum[r] += pv;
            if (lane == 0) prow[lrow[r] * JP + j] = pv;
        }
    }

    const int j0 = lane, j1 = lane + 32, j2 = lane + 64;
    const float ra0 = ra_sm[j0], ra1 = ra_sm[j1], ra2 = ra_sm[j2];
    float b0[R], b1[R], b2[R];
#pragma unroll
    for (int r = 0; r < R; r++) {
        const float* bp = bias + (base + lrow[r]) * Kn;
        b0[r] = bp[j0]; b1[r] = bp[j1]; b2[r] = bp[j2];
    }

    // ---- main scores loop: 3 fma-instr per row per e (unroll 2) ----
    float acc0[R], acc1[R], acc2[R];
#pragma unroll
    for (int r = 0; r < R; r++) { acc0[r] = acc1[r] = acc2[r] = 0.f; }

#pragma unroll 2
    for (int e4 = 0; e4 < En / 4; e4++) {
        float4 a4 = *(const float4*)(a04 + 4 * e4);
        float4 u4[R];
#pragma unroll
        for (int r = 0; r < R; r++)
            u4[r] = *(const float4*)(u_sm + lrow[r] * En + 4 * e4);
#pragma unroll
        for (int sub = 0; sub < 4; sub++) {
            int e = 4 * e4 + sub;
            float r0 = R_sm[e * JP + j0];
            float r1 = R_sm[e * JP + j1];
            float r2 = R_sm[e * JP + j2];
            float av = (sub == 0) ? a4.x : (sub == 1) ? a4.y
                     : (sub == 2) ? a4.z : a4.w;
#pragma unroll
            for (int r = 0; r < R; r++) {
                float uv = (sub == 0) ? u4[r].x : (sub == 1) ? u4[r].y
                         : (sub == 2) ? u4[r].z : u4[r].w;
                acc0[r] = fmaf(fabsf(uv + r0), av, acc0[r]);
                acc1[r] = fmaf(fabsf(uv + r1), av, acc1[r]);
                acc2[r] = fmaf(fabsf(uv + r2), av, acc2[r]);
            }
        }
    }

    // ---- softmax per row ----
    float rinv[R];
#pragma unroll
    for (int r = 0; r < R; r++) {
        float p0 = __expf(aua[r] + ra0 + acc0[r] + b0[r]);
        float p1 = __expf(aua[r] + ra1 + acc1[r] + b1[r]);
        float p2 = __expf(aua[r] + ra2 + acc2[r] + b2[r]);
        float ps = p0 + p1 + p2;
#pragma unroll
        for (int o = 16; o; o >>= 1) ps += __shfl_xor_sync(0xffffffffu, ps, o);
        prow[lrow[r] * JP + j0] = p0;
        prow[lrow[r] * JP + j1] = p1;
        prow[lrow[r] * JP + j2] = p2;
        rinv[r] = 1.0f / (ps + side_sum[r]);
    }
    __syncwarp();

    // ---- attn @ x : lane owns f-quad; p loaded as float4 per 4 j ----
    float4 h[R];
#pragma unroll
    for (int r = 0; r < R; r++) h[r] = make_float4(0.f, 0.f, 0.f, 0.f);
    const float* xc = xs + 4 * lane;
#pragma unroll 5
    for (int jq = 0; jq < Kn / 4; jq++) {
        float4 p4[R];
#pragma unroll
        for (int r = 0; r < R; r++)
            p4[r] = *(const float4*)(prow + lrow[r] * JP + 4 * jq);
#pragma unroll
        for (int c = 0; c < 4; c++) {
            float4 xv = *(const float4*)(xc + (4 * jq + c) * Fn);
#pragma unroll
            for (int r = 0; r < R; r++) {
                float pj = (c == 0) ? p4[r].x : (c == 1) ? p4[r].y
                         : (c == 2) ? p4[r].z : p4[r].w;
                h[r].x = fmaf(pj, xv.x, h[r].x);
                h[r].y = fmaf(pj, xv.y, h[r].y);
                h[r].z = fmaf(pj, xv.z, h[r].z);
                h[r].w = fmaf(pj, xv.w, h[r].w);
            }
        }
    }
#pragma unroll
    for (int r = 0; r < R; r++) {
        int i = base + lrow[r];
        float ri = rinv[r];
        float4 o4;
        o4.x = 1.0f / (1.0f + __expf(-h[r].x * ri));
        o4.y = 1.0f / (1.0f + __expf(-h[r].y * ri));
        o4.z = 1.0f / (1.0f + __expf(-h[r].z * ri));
        o4.w = 1.0f / (1.0f + __expf(-h[r].w * ri));
        *(float4*)(out + (b * Kn + i) * Fn + 4 * lane) = o4;
    }
}

__global__ __launch_bounds__(768, 1)
void attn_kernel(const float* __restrict__ x,
                 const float* __restrict__ avec,
                 const float* __restrict__ bvec,
                 const float* __restrict__ bias,
                 float* __restrict__ out) {
    extern __shared__ float sm[];
    float* R_sm  = sm;                    // En*JP = 25600 f
    float* xs    = R_sm + En * JP;        // Kn*Fn = 12800 f
    float* u_sm  = xs + Kn * Fn;          // 52*En = 10400 f
    float* prow  = u_sm + 52 * En;        // 52*JP =  6656 f
    float* a04   = prow + 52 * JP;        // En
    float* ra_sm = a04 + En;              // JP
    float* Rside = ra_sm + JP;            // 4*201 = 804 f

    const int b     = blockIdx.x;
    const int base  = blockIdx.y ? 52 : 0;
    const int nrows = blockIdx.y ? 48 : 52;
    const int tid   = threadIdx.x;
    const int wid   = tid >> 5, lane = tid & 31;

    {   // R: first En*JP floats of the batch's region are contiguous
        const float4* src = (const float4*)(g_RT + b * EP * JP);
        float4* dst = (float4*)R_sm;
        const float4 z4 = {0.f, 0.f, 0.f, 0.f};
        for (int idx = tid; idx < En * (JP / 4); idx += 768) {
            int q = idx & 31;
            dst[idx] = (q < 25) ? src[idx] : z4;
        }
    }
    {
        const float4* src = (const float4*)(x + b * Kn * Fn);
        float4* dst = (float4*)xs;
        for (int idx = tid; idx < Kn * Fn / 4; idx += 768) dst[idx] = src[idx];
    }
    {   // u rows from g_UL (row stride EP), adding lin-bias bvec
        const float4* src = (const float4*)(g_UL + (b * MT + base) * EP);
        float4* dst = (float4*)u_sm;
        for (int idx = tid; idx < nrows * (En / 4); idx += 768) {
            int r = idx / 50, q = idx - r * 50;
            float4 v = src[r * (EP / 4) + q];
            float4 bv = __ldg((const float4*)bvec + q);
            v.x += bv.x; v.y += bv.y; v.z += bv.z; v.w += bv.w;
            dst[idx] = v;
        }
    }
    {   // compact side copy: Rside[js][e] = R[e][96+js]
        const float* src = g_RT + b * EP * JP;
        for (int idx = tid; idx < 4 * En; idx += 768) {
            int js = idx / En, e = idx - js * En;
            Rside[js * 201 + e] = src[e * JP + 96 + js];
        }
    }
    for (int e = tid; e < En; e += 768) a04[e] = 0.4f * avec[e];
    __syncthreads();

    if (wid < 16) {
        int j = 8 * wid + (lane & 7);
        int s0 = lane >> 3;
        float s = 0.f;
        const float* rc = R_sm + j;
        for (int e = s0; e < En; e += 4) s = fmaf(rc[e * JP], a04[e], s);
        s += __shfl_xor_sync(0xffffffffu, s, 8);
        s += __shfl_xor_sync(0xffffffffu, s, 16);
        if (lane < 8) ra_sm[j] = 1.5f * s;
    }
    __syncthreads();

    int lrow[3] = {wid, wid + 24, wid + 48};
    if (wid + 48 < nrows)
        do_rows<3>(R_sm, xs, u_sm, prow, a04, ra_sm, Rside, lrow, base, b, lane, bias, out);
    else if (wid + 24 < nrows)
        do_rows<2>(R_sm, xs, u_sm, prow, a04, ra_sm, Rside, lrow, base, b, lane, bias, out);
    else if (wid < nrows)
        do_rows<1>(R_sm, xs, u_sm, prow, a04, ra_sm, Rside, lrow, base, b, lane, bias, out);
}

// ---------------------------------------------------------------------------
extern "C" void kernel_launch(void* const* d_in, const int* in_sizes, int n_in,
                              void* d_out, int out_size) {
    const float* x    = (const float*)d_in[0];
    const float* W    = (const float*)d_in[1];
    const float* bvec = (const float*)d_in[2];
    const float* avec = (const float*)d_in[3];
    const float* bias = (const float*)d_in[4];
    float* out = (float*)d_out;

    const size_t smemP = (size_t)(2 * MT * LDA + 2 * Fn * LDB)
                         * sizeof(__nv_bfloat16)
                         + (size_t)(64 * LDR) * sizeof(float);         // ~191.5 KB
    const size_t smem2 = (En * JP + Kn * Fn + 52 * En + 52 * JP + En + JP
                          + 4 * 201) * sizeof(float);                  // ~226.3 KB

    cudaFuncSetAttribute(proj_wmma, cudaFuncAttributeMaxDynamicSharedMemorySize,
                         (int)smemP);
    cudaFuncSetAttribute(attn_kernel, cudaFuncAttributeMaxDynamicSharedMemorySize,
                         (int)smem2);

    proj_wmma<<<dim3(Bn, 2), 768, smemP>>>(x, W);
    attn_kernel<<<dim3(Bn, 2), 768, smem2>>>(x, avec, bvec, bias, out);
}

// round 17
// speedup vs baseline: 1.0475x; 1.0475x over previous
#include <cuda_runtime.h>
#include <cuda_bf16.h>
#include <mma.h>
using namespace nvcuda;

constexpr int Bn = 64, Kn = 100, Fn = 128, En = 200, JP = 128;
constexpr int EP = 208;                 // padded E (13 n-tiles)
constexpr int MT = 112;                 // padded M (7 m-tiles)
constexpr int LDA = 136, LDB = 208;     // smem leading dims (mult of 8 bf16)

__device__ float g_UL[Bn * MT * EP];    // left proj (NO bias), row-major [b][row][e]
__device__ float g_RT[Bn * EP * JP];    // right proj transposed: [b][e][j]

// ---------------------------------------------------------------------------
// Kernel 1 (R15 version, measured ~16.5us): 3-pass bf16 split-precision WMMA.
// Block = (batch b, chunk c). D[112x208] = x_b[112(pad)x128] @ Wc[128x208(pad)]
// W converted to bf16 hi/lo inline during staging (L2-served).
// chunk0 -> g_UL (row_major), chunk1 -> g_RT (col_major = transposed).
// Ends with PDL trigger so attn may begin its independent staging.
// ---------------------------------------------------------------------------
__global__ __launch_bounds__(768, 1)
void proj_wmma(const float* __restrict__ x, const float* __restrict__ W) {
    extern __shared__ char smc[];
    __nv_bfloat16* a_hi = (__nv_bfloat16*)smc;        // 112 x 136
    __nv_bfloat16* a_lo = a_hi + MT * LDA;
    __nv_bfloat16* b_hi = a_lo + MT * LDA;            // 128 x 208
    __nv_bfloat16* b_lo = b_hi + Fn * LDB;

    const int b = blockIdx.x, chunk = blockIdx.y;
    const int tid = threadIdx.x, wid = tid >> 5;

    const __nv_bfloat16 zb = __float2bfloat16(0.f);
    for (int i = tid; i < MT * LDA / 2; i += 768) {
        ((__nv_bfloat162*)a_hi)[i] = __nv_bfloat162{zb, zb};
        ((__nv_bfloat162*)a_lo)[i] = __nv_bfloat162{zb, zb};
    }
    for (int i = tid; i < Fn * 8; i += 768) {
        int k = i >> 3, c = En + (i & 7);
        b_hi[k * LDB + c] = zb;
        b_lo[k * LDB + c] = zb;
    }
    __syncthreads();
    {   // stage x -> hi/lo (vectorized)
        const float4* src = (const float4*)(x + b * Kn * Fn);
        for (int idx = tid; idx < Kn * Fn / 4; idx += 768) {
            int r = idx >> 5, kq = idx & 31;
            float4 v = src[idx];
            float vf[4] = {v.x, v.y, v.z, v.w};
            __nv_bfloat16 h[4], l[4];
#pragma unroll
            for (int c = 0; c < 4; c++) {
                h[c] = __float2bfloat16(vf[c]);
                l[c] = __float2bfloat16(vf[c] - __bfloat162float(h[c]));
            }
            int o = r * LDA + 4 * kq;
            *(__nv_bfloat162*)(a_hi + o)     = __nv_bfloat162{h[0], h[1]};
            *(__nv_bfloat162*)(a_hi + o + 2) = __nv_bfloat162{h[2], h[3]};
            *(__nv_bfloat162*)(a_lo + o)     = __nv_bfloat162{l[0], l[1]};
            *(__nv_bfloat162*)(a_lo + o + 2) = __nv_bfloat162{l[2], l[3]};
        }
    }
    {   // stage + convert W chunk (cols 0..199)
        const float4* src = (const float4*)(W + chunk * Fn * En);
        for (int idx = tid; idx < Fn * En / 4; idx += 768) {
            int k = idx / 50, q = idx - k * 50;
            float4 v = src[idx];
            float vf[4] = {v.x, v.y, v.z, v.w};
            __nv_bfloat16 h[4], l[4];
#pragma unroll
            for (int c = 0; c < 4; c++) {
                h[c] = __float2bfloat16(vf[c]);
                l[c] = __float2bfloat16(vf[c] - __bfloat162float(h[c]));
            }
            int o = k * LDB + 4 * q;
            *(__nv_bfloat162*)(b_hi + o)     = __nv_bfloat162{h[0], h[1]};
            *(__nv_bfloat162*)(b_hi + o + 2) = __nv_bfloat162{h[2], h[3]};
            *(__nv_bfloat162*)(b_lo + o)     = __nv_bfloat162{l[0], l[1]};
            *(__nv_bfloat162*)(b_lo + o + 2) = __nv_bfloat162{l[2], l[3]};
        }
    }
    __syncthreads();

    for (int t = wid; t < 7 * 13; t += 24) {
        int tm = t / 13, tn = t - tm * 13;
        wmma::fragment<wmma::accumulator, 16, 16, 16, float> acc;
        wmma::fill_fragment(acc, 0.f);
#pragma unroll
        for (int kt = 0; kt < 8; kt++) {
            wmma::fragment<wmma::matrix_a, 16, 16, 16, __nv_bfloat16, wmma::row_major> ah, al;
            wmma::fragment<wmma::matrix_b, 16, 16, 16, __nv_bfloat16, wmma::row_major> bh, bl;
            wmma::load_matrix_sync(ah, a_hi + tm * 16 * LDA + kt * 16, LDA);
            wmma::load_matrix_sync(al, a_lo + tm * 16 * LDA + kt * 16, LDA);
            wmma::load_matrix_sync(bh, b_hi + kt * 16 * LDB + tn * 16, LDB);
            wmma::load_matrix_sync(bl, b_lo + kt * 16 * LDB + tn * 16, LDB);
            wmma::mma_sync(acc, ah, bh, acc);
            wmma::mma_sync(acc, ah, bl, acc);
            wmma::mma_sync(acc, al, bh, acc);
        }
        if (chunk == 0) {
            float* dst = g_UL + b * MT * EP + tm * 16 * EP + tn * 16;
            wmma::store_matrix_sync(dst, acc, EP, wmma::mem_row_major);
        } else {
            float* dst = g_RT + b * EP * JP + tn * 16 * JP + tm * 16;
            wmma::store_matrix_sync(dst, acc, JP, wmma::mem_col_major);
        }
    }

#if __CUDA_ARCH__ >= 900
    cudaTriggerProgrammaticLaunchCompletion();
#endif
}

// ---------------------------------------------------------------------------
// Kernel 2 (R15 compute, measured 37.6us): trio j-mapping.
// lane owns j in {lane, lane+32, lane+64}; j = 96..99 via side dot-products
// BEFORE the main loop; main e4 loop at unroll 2.
// leaky(z) = 0.6 z + 0.4 |z|:
// e_ij = 1.5*(ua04_i + ra04_j) + sum_e a04_e * |u_ie + R_ej| + bias_ij
// Staging split: independent (x, avec) before grid-dep sync; dependent after.
// ---------------------------------------------------------------------------
template <int R>
__device__ __forceinline__ void do_rows(
    const float* R_sm, const float* xs, const float* u_sm, float* prow,
    const float* a04, const float* ra_sm, const float* Rside,
    const int* lrow, int base, int b, int lane,
    const float* __restrict__ bias, float* __restrict__ out) {

    // aua = 1.5 * (u_r . a04)
    float aua[R];
#pragma unroll
    for (int r = 0; r < R; r++) {
        float s = 0.f;
        const float* up = u_sm + lrow[r] * En;
        for (int e = lane; e < En; e += 32) s = fmaf(up[e], a04[e], s);
#pragma unroll
        for (int o = 16; o; o >>= 1) s += __shfl_xor_sync(0xffffffffu, s, o);
        aua[r] = 1.5f * s;
    }

    // side scores j = 96..99 (conflict-free Rside[js][201])
    float side_sum[R];
#pragma unroll
    for (int r = 0; r < R; r++) {
        side_sum[r] = 0.f;
        const float* up = u_sm + lrow[r] * En;
        const float* bp = bias + (base + lrow[r]) * Kn;
#pragma unroll
        for (int js = 0; js < 4; js++) {
            const float* rs = Rside + js * 201;
            float s = 0.f;
            for (int e = lane; e < En; e += 32)
                s = fmaf(fabsf(up[e] + rs[e]), a04[e], s);
#pragma unroll
            for (int o = 16; o; o >>= 1) s += __shfl_xor_sync(0xffffffffu, s, o);
            int j = 96 + js;
            float pv = __expf(aua[r] + ra_sm[j] + s + bp[j]);
            side_sum[r] += pv;
            if (lane == 0) prow[lrow[r] * JP + j] = pv;
        }
    }

    const int j0 = lane, j1 = lane + 32, j2 = lane + 64;
    const float ra0 = ra_sm[j0], ra1 = ra_sm[j1], ra2 = ra_sm[j2];
    float b0[R], b1[R], b2[R];
#pragma unroll
    for (int r = 0; r < R; r++) {
        const float* bp = bias + (base + lrow[r]) * Kn;
        b0[r] = bp[j0]; b1[r] = bp[j1]; b2[r] = bp[j2];
    }

    // ---- main scores loop: 3 fma-instr per row per e (unroll 2) ----
    float acc0[R], acc1[R], acc2[R];
#pragma unroll
    for (int r = 0; r < R; r++) { acc0[r] = acc1[r] = acc2[r] = 0.f; }

#pragma unroll 2
    for (int e4 = 0; e4 < En / 4; e4++) {
        float4 a4 = *(const float4*)(a04 + 4 * e4);
        float4 u4[R];
#pragma unroll
        for (int r = 0; r < R; r++)
            u4[r] = *(const float4*)(u_sm + lrow[r] * En + 4 * e4);
#pragma unroll
        for (int sub = 0; sub < 4; sub++) {
            int e = 4 * e4 + sub;
            float r0 = R_sm[e * JP + j0];
            float r1 = R_sm[e * JP + j1];
            float r2 = R_sm[e * JP + j2];
            float av = (sub == 0) ? a4.x : (sub == 1) ? a4.y
                     : (sub == 2) ? a4.z : a4.w;
#pragma unroll
            for (int r = 0; r < R; r++) {
                float uv = (sub == 0) ? u4[r].x : (sub == 1) ? u4[r].y
                         : (sub == 2) ? u4[r].z : u4[r].w;
                acc0[r] = fmaf(fabsf(uv + r0), av, acc0[r]);
                acc1[r] = fmaf(fabsf(uv + r1), av, acc1[r]);
                acc2[r] = fmaf(fabsf(uv + r2), av, acc2[r]);
            }
        }
    }

    // ---- softmax per row ----
    float rinv[R];
#pragma unroll
    for (int r = 0; r < R; r++) {
        float p0 = __expf(aua[r] + ra0 + acc0[r] + b0[r]);
        float p1 = __expf(aua[r] + ra1 + acc1[r] + b1[r]);
        float p2 = __expf(aua[r] + ra2 + acc2[r] + b2[r]);
        float ps = p0 + p1 + p2;
#pragma unroll
        for (int o = 16; o; o >>= 1) ps += __shfl_xor_sync(0xffffffffu, ps, o);
        prow[lrow[r] * JP + j0] = p0;
        prow[lrow[r] * JP + j1] = p1;
        prow[lrow[r] * JP + j2] = p2;
        rinv[r] = 1.0f / (ps + side_sum[r]);
    }
    __syncwarp();

    // ---- attn @ x : lane owns f-quad; p loaded as float4 per 4 j ----
    float4 h[R];
#pragma unroll
    for (int r = 0; r < R; r++) h[r] = make_float4(0.f, 0.f, 0.f, 0.f);
    const float* xc = xs + 4 * lane;
#pragma unroll 5
    for (int jq = 0; jq < Kn / 4; jq++) {
        float4 p4[R];
#pragma unroll
        for (int r = 0; r < R; r++)
            p4[r] = *(const float4*)(prow + lrow[r] * JP + 4 * jq);
#pragma unroll
        for (int c = 0; c < 4; c++) {
            float4 xv = *(const float4*)(xc + (4 * jq + c) * Fn);
#pragma unroll
            for (int r = 0; r < R; r++) {
                float pj = (c == 0) ? p4[r].x : (c == 1) ? p4[r].y
                         : (c == 2) ? p4[r].z : p4[r].w;
                h[r].x = fmaf(pj, xv.x, h[r].x);
                h[r].y = fmaf(pj, xv.y, h[r].y);
                h[r].z = fmaf(pj, xv.z, h[r].z);
                h[r].w = fmaf(pj, xv.w, h[r].w);
            }
        }
    }
#pragma unroll
    for (int r = 0; r < R; r++) {
        int i = base + lrow[r];
        float ri = rinv[r];
        float4 o4;
        o4.x = 1.0f / (1.0f + __expf(-h[r].x * ri));
        o4.y = 1.0f / (1.0f + __expf(-h[r].y * ri));
        o4.z = 1.0f / (1.0f + __expf(-h[r].z * ri));
        o4.w = 1.0f / (1.0f + __expf(-h[r].w * ri));
        *(float4*)(out + (b * Kn + i) * Fn + 4 * lane) = o4;
    }
}

__global__ __launch_bounds__(768, 1)
void attn_kernel(const float* __restrict__ x,
                 const float* __restrict__ avec,
                 const float* __restrict__ bvec,
                 const float* __restrict__ bias,
                 float* __restrict__ out) {
    extern __shared__ float sm[];
    float* R_sm  = sm;                    // En*JP = 25600 f
    float* xs    = R_sm + En * JP;        // Kn*Fn = 12800 f
    float* u_sm  = xs + Kn * Fn;          // 52*En = 10400 f
    float* prow  = u_sm + 52 * En;        // 52*JP =  6656 f
    float* a04   = prow + 52 * JP;        // En
    float* ra_sm = a04 + En;              // JP
    float* Rside = ra_sm + JP;            // 4*201 = 804 f

    const int b     = blockIdx.x;
    const int base  = blockIdx.y ? 52 : 0;
    const int nrows = blockIdx.y ? 48 : 52;
    const int tid   = threadIdx.x;
    const int wid   = tid >> 5, lane = tid & 31;

    // ---- independent staging (x, avec) — runs under PDL overlap ----
    {
        const float4* src = (const float4*)(x + b * Kn * Fn);
        float4* dst = (float4*)xs;
        for (int idx = tid; idx < Kn * Fn / 4; idx += 768) dst[idx] = src[idx];
    }
    for (int e = tid; e < En; e += 768) a04[e] = 0.4f * avec[e];

#if __CUDA_ARCH__ >= 900
    cudaGridDependencySynchronize();      // wait for proj's g_UL / g_RT
#endif

    // ---- dependent staging ----
    {   // R: first En*JP floats of the batch's region are contiguous
        const float4* src = (const float4*)(g_RT + b * EP * JP);
        float4* dst = (float4*)R_sm;
        const float4 z4 = {0.f, 0.f, 0.f, 0.f};
        for (int idx = tid; idx < En * (JP / 4); idx += 768) {
            int q = idx & 31;
            dst[idx] = (q < 25) ? src[idx] : z4;
        }
    }
    {   // u rows from g_UL (row stride EP), adding lin-bias bvec
        const float4* src = (const float4*)(g_UL + (b * MT + base) * EP);
        float4* dst = (float4*)u_sm;
        for (int idx = tid; idx < nrows * (En / 4); idx += 768) {
            int r = idx / 50, q = idx - r * 50;
            float4 v = src[r * (EP / 4) + q];
            float4 bv = __ldg((const float4*)bvec + q);
            v.x += bv.x; v.y += bv.y; v.z += bv.z; v.w += bv.w;
            dst[idx] = v;
        }
    }
    {   // compact side copy: Rside[js][e] = R[e][96+js]
        const float* src = g_RT + b * EP * JP;
        for (int idx = tid; idx < 4 * En; idx += 768) {
            int js = idx / En, e = idx - js * En;
            Rside[js * 201 + e] = src[e * JP + 96 + js];
        }
    }
    __syncthreads();

    if (wid < 16) {
        int j = 8 * wid + (lane & 7);
        int s0 = lane >> 3;
        float s = 0.f;
        const float* rc = R_sm + j;
        for (int e = s0; e < En; e += 4) s = fmaf(rc[e * JP], a04[e], s);
        s += __shfl_xor_sync(0xffffffffu, s, 8);
        s += __shfl_xor_sync(0xffffffffu, s, 16);
        if (lane < 8) ra_sm[j] = 1.5f * s;
    }
    __syncthreads();

    int lrow[3] = {wid, wid + 24, wid + 48};
    if (wid + 48 < nrows)
        do_rows<3>(R_sm, xs, u_sm, prow, a04, ra_sm, Rside, lrow, base, b, lane, bias, out);
    else if (wid + 24 < nrows)
        do_rows<2>(R_sm, xs, u_sm, prow, a04, ra_sm, Rside, lrow, base, b, lane, bias, out);
    else if (wid < nrows)
        do_rows<1>(R_sm, xs, u_sm, prow, a04, ra_sm, Rside, lrow, base, b, lane, bias, out);
}

// ---------------------------------------------------------------------------
extern "C" void kernel_launch(void* const* d_in, const int* in_sizes, int n_in,
                              void* d_out, int out_size) {
    const float* x    = (const float*)d_in[0];
    const float* W    = (const float*)d_in[1];
    const float* bvec = (const float*)d_in[2];
    const float* avec = (const float*)d_in[3];
    const float* bias = (const float*)d_in[4];
    float* out = (float*)d_out;

    const size_t smemP = (size_t)(2 * MT * LDA + 2 * Fn * LDB)
                         * sizeof(__nv_bfloat16);                      // ~163.5 KB
    const size_t smem2 = (En * JP + Kn * Fn + 52 * En + 52 * JP + En + JP
                          + 4 * 201) * sizeof(float);                  // ~226.3 KB

    cudaFuncSetAttribute(proj_wmma, cudaFuncAttributeMaxDynamicSharedMemorySize,
                         (int)smemP);
    cudaFuncSetAttribute(attn_kernel, cudaFuncAttributeMaxDynamicSharedMemorySize,
                         (int)smem2);

    proj_wmma<<<dim3(Bn, 2), 768, smemP>>>(x, W);

    // attn with PDL: launch overlaps proj tail; device syncs before dependent reads
    cudaLaunchConfig_t cfg = {};
    cfg.gridDim = dim3(Bn, 2);
    cfg.blockDim = dim3(768, 1, 1);
    cfg.dynamicSmemBytes = smem2;
    cfg.stream = 0;
    cudaLaunchAttribute at[1];
    at[0].id = cudaLaunchAttributeProgrammaticStreamSerialization;
    at[0].val.programmaticStreamSerializationAllowed = 1;
    cfg.attrs = at;
    cfg.numAttrs = 1;
    cudaLaunchKernelEx(&cfg, attn_kernel, x, avec, bvec, bias, out);
}